// round 16
// baseline (speedup 1.0000x reference)
#include <cuda_runtime.h>
#include <cuda_fp16.h>
#include <math.h>

#define MAXN 100000
#define MAXE 1600000

// ---------------- static device scratch (device-code use ONLY) -----------------
__device__ int    g_deg[MAXN];
__device__ int    g_off[MAXN + 1];
__device__ int    g_cur[MAXN];
__device__ int    g_part[1024];
__device__ int    g_srcA[MAXE];       // CSR: incoming-edge sources per dst node
__device__ float  g_norm[MAXN];
__device__ __half g_t[MAXN * 64];     // messages: h * norm (fp16)
__device__ __half g_agg[MAXN * 64];   // aggregation output * norm (fp16, rn — same as old staging)

// ---------------- graph preprocessing ------------------------------------------
__global__ void kz_deg(int n) {
    int i = blockIdx.x * blockDim.x + threadIdx.x;
    if (i < n) g_deg[i] = 0;
}
__global__ void kfill_out(float* __restrict__ p, int c) {
    int i = blockIdx.x * blockDim.x + threadIdx.x;
    if (i < c) p[i] = 0.0f;
}
__global__ void kdeg(const int* __restrict__ dst, int E) {
    int e = blockIdx.x * blockDim.x + threadIdx.x;
    if (e < E) atomicAdd(&g_deg[dst[e]], 1);
}

// ---- 3-pass exclusive scan of g_deg[0..N) -> g_off, g_cur (+norm in pass 3) ----
__global__ void kscan1(int N) {
    __shared__ int sh[1024];
    int tid = threadIdx.x;
    int i = blockIdx.x * 1024 + tid;
    int v = (i < N) ? g_deg[i] : 0;
    sh[tid] = v;
    __syncthreads();
    for (int off = 1; off < 1024; off <<= 1) {
        int t = (tid >= off) ? sh[tid - off] : 0;
        __syncthreads();
        sh[tid] += t;
        __syncthreads();
    }
    if (i < N) g_off[i] = sh[tid] - v;
    if (tid == 1023) g_part[blockIdx.x] = sh[1023];
}
__global__ void kscan2(int nb, int N) {
    __shared__ int sh[1024];
    int tid = threadIdx.x;
    int v = (tid < nb) ? g_part[tid] : 0;
    sh[tid] = v;
    __syncthreads();
    for (int off = 1; off < 1024; off <<= 1) {
        int t = (tid >= off) ? sh[tid - off] : 0;
        __syncthreads();
        sh[tid] += t;
        __syncthreads();
    }
    if (tid < nb) g_part[tid] = sh[tid] - v;
    if (tid == 1023) g_off[N] = sh[1023];
}
__global__ void kscan3(int N) {
    int i = blockIdx.x * 1024 + threadIdx.x;
    if (i < N) {
        int o = g_off[i] + g_part[blockIdx.x];
        g_off[i] = o;
        g_cur[i] = o;
        g_norm[i] = rsqrtf(fmaxf((float)g_deg[i], 1.0f));
    }
}

__global__ void kcsr(const int* __restrict__ src, const int* __restrict__ dst, int E) {
    int e = blockIdx.x * blockDim.x + threadIdx.x;
    if (e < E) {
        int p = atomicAdd(&g_cur[dst[e]], 1);
        g_srcA[p] = src[e];
    }
}

__global__ void kt0(const float* __restrict__ x, int c) {
    int i = blockIdx.x * blockDim.x + threadIdx.x;
    if (i < c) g_t[i] = __float2half_rn(x[i] * g_norm[i >> 6]);
}

// ---------------- aggregation (pull over CSR, fp16 msgs, fp32 accum) ------------
// one warp per dst node; lane owns one half2 (2 feats). 16-deep MLP main loop,
// CSR indices via aligned int4 (peel to 4-alignment first).
__global__ __launch_bounds__(256) void kagg64(int N) {
    int n = blockIdx.x * 8 + (threadIdx.x >> 5);
    if (n >= N) return;
    int lane = threadIdx.x & 31;
    int b = g_off[n], e = g_off[n + 1];
    const __half2* tp = (const __half2*)g_t;
    float ax = 0.f, ay = 0.f;

    int i = b;
    int lim = (b + 3) & ~3;
    if (lim > e) lim = e;
    for (; i < lim; i++) {                         // peel to 4-int alignment
        float2 v = __half22float2(tp[g_srcA[i] * 32 + lane]);
        ax += v.x; ay += v.y;
    }
    for (; i + 16 <= e; i += 16) {
        int4 sa = *(const int4*)(g_srcA + i);
        int4 sb = *(const int4*)(g_srcA + i + 4);
        int4 sc = *(const int4*)(g_srcA + i + 8);
        int4 sd = *(const int4*)(g_srcA + i + 12);
        int s[16] = {sa.x, sa.y, sa.z, sa.w, sb.x, sb.y, sb.z, sb.w,
                     sc.x, sc.y, sc.z, sc.w, sd.x, sd.y, sd.z, sd.w};
        float2 f[16];
#pragma unroll
        for (int u = 0; u < 16; u++) f[u] = __half22float2(tp[s[u] * 32 + lane]);
#pragma unroll
        for (int u = 0; u < 16; u++) { ax += f[u].x; ay += f[u].y; }
    }
    for (; i + 4 <= e; i += 4) {
        int4 sa = *(const int4*)(g_srcA + i);
        float2 f0 = __half22float2(tp[sa.x * 32 + lane]);
        float2 f1 = __half22float2(tp[sa.y * 32 + lane]);
        float2 f2 = __half22float2(tp[sa.z * 32 + lane]);
        float2 f3 = __half22float2(tp[sa.w * 32 + lane]);
        ax += f0.x + f1.x + f2.x + f3.x;
        ay += f0.y + f1.y + f2.y + f3.y;
    }
    for (; i < e; i++) {
        float2 v = __half22float2(tp[g_srcA[i] * 32 + lane]);
        ax += v.x; ay += v.y;
    }
    float nm = g_norm[n];
    ((__half2*)g_agg)[n * 32 + lane] = __floats2half2_rn(ax * nm, ay * nm);
}

// 32 feats: lane owns 1 half
__global__ __launch_bounds__(256) void kagg32(int N) {
    int n = blockIdx.x * 8 + (threadIdx.x >> 5);
    if (n >= N) return;
    int lane = threadIdx.x & 31;
    int b = g_off[n], e = g_off[n + 1];
    float a = 0.f;

    int i = b;
    int lim = (b + 3) & ~3;
    if (lim > e) lim = e;
    for (; i < lim; i++) a += __half2float(g_t[g_srcA[i] * 32 + lane]);
    for (; i + 16 <= e; i += 16) {
        int4 sa = *(const int4*)(g_srcA + i);
        int4 sb = *(const int4*)(g_srcA + i + 4);
        int4 sc = *(const int4*)(g_srcA + i + 8);
        int4 sd = *(const int4*)(g_srcA + i + 12);
        int s[16] = {sa.x, sa.y, sa.z, sa.w, sb.x, sb.y, sb.z, sb.w,
                     sc.x, sc.y, sc.z, sc.w, sd.x, sd.y, sd.z, sd.w};
        float f[16];
#pragma unroll
        for (int u = 0; u < 16; u++) f[u] = __half2float(g_t[s[u] * 32 + lane]);
#pragma unroll
        for (int u = 0; u < 16; u++) a += f[u];
    }
    for (; i + 4 <= e; i += 4) {
        int4 sa = *(const int4*)(g_srcA + i);
        a += __half2float(g_t[sa.x * 32 + lane]) + __half2float(g_t[sa.y * 32 + lane]) +
             __half2float(g_t[sa.z * 32 + lane]) + __half2float(g_t[sa.w * 32 + lane]);
    }
    for (; i < e; i++) a += __half2float(g_t[g_srcA[i] * 32 + lane]);
    g_agg[n * 32 + lane] = __float2half_rn(a * g_norm[n]);
}

// ---------------- tensor-core GEMM (HMMA fp16 x fp16 -> fp32) -------------------
// 256 threads = 8 warps; tile 128 nodes x 64 outs; warp w owns nodes [w*16, w*16+16).
// A: g_agg fp16 -> smem [128][K] (stride K+8, pure 16B copies). B: W row-major fp32
// -> fp16 smem [64][K] — col-major B for mma row.col.
template <int K, int EPI>
__global__ __launch_bounds__(256) void kgemm(
    const float* __restrict__ Wa, const float* __restrict__ Wb,
    const float* __restrict__ bias0, const float* __restrict__ bias1,
    float* __restrict__ o0, float* __restrict__ o1, const float* __restrict__ eps,
    int N, int have)
{
    constexpr int ASTR = K + 8;                 // halves, keeps rows 16B aligned
    extern __shared__ __half smh[];
    __half* Ah = smh;                           // 128 * ASTR
    __half* Wh = smh + 128 * ASTR;              // 64 * ASTR
    float* Bsm = (float*)(Wh + 64 * ASTR);      // 64
    const int tid = threadIdx.x;
    const int base = blockIdx.x * 128;

    // stage A tile: straight 16B copies from fp16 g_agg
    for (int q = tid; q < 128 * (K / 8); q += 256) {
        int node = q / (K / 8), seg = q % (K / 8);
        int gn = base + node;
        uint4 v = make_uint4(0u, 0u, 0u, 0u);
        if (gn < N) v = *(const uint4*)(g_agg + (long long)gn * K + seg * 8);
        *(uint4*)(Ah + node * ASTR + seg * 8) = v;
    }
    // stage W (fp32 -> fp16)
    for (int q = tid; q < 64 * (K / 8); q += 256) {
        int o = q / (K / 8), seg = q % (K / 8);
        const float* Wrow;
        if (EPI == 1) Wrow = (o < 32) ? (Wa + o * 64) : (Wb + (o - 32) * 64);
        else          Wrow = Wa + o * K;
        float4 v0 = *(const float4*)(Wrow + seg * 8);
        float4 v1 = *(const float4*)(Wrow + seg * 8 + 4);
        __half2 h[4];
        h[0] = __floats2half2_rn(v0.x, v0.y);
        h[1] = __floats2half2_rn(v0.z, v0.w);
        h[2] = __floats2half2_rn(v1.x, v1.y);
        h[3] = __floats2half2_rn(v1.z, v1.w);
        *(uint4*)(Wh + o * ASTR + seg * 8) = *(uint4*)h;
    }
    if (tid < 64) {
        if (EPI == 1) Bsm[tid] = (tid < 32) ? bias0[tid] : bias1[tid - 32];
        else          Bsm[tid] = bias0[tid];
    }
    __syncthreads();

    const int w = tid >> 5, lane = tid & 31;
    const int m0 = w * 16;

    float acc[8][4];
#pragma unroll
    for (int nt = 0; nt < 8; nt++)
#pragma unroll
        for (int j = 0; j < 4; j++) acc[nt][j] = 0.f;

#pragma unroll
    for (int kk = 0; kk < K; kk += 16) {
        unsigned a0, a1, a2, a3;
        {
            int row = m0 + (lane & 15);
            int col = kk + ((lane >> 4) << 3);
            unsigned sa = (unsigned)__cvta_generic_to_shared(Ah + row * ASTR + col);
            asm volatile("ldmatrix.sync.aligned.m8n8.x4.shared.b16 {%0,%1,%2,%3}, [%4];"
                         : "=r"(a0), "=r"(a1), "=r"(a2), "=r"(a3) : "r"(sa));
        }
#pragma unroll
        for (int nt = 0; nt < 8; nt++) {
            unsigned b0, b1;
            int brow = nt * 8 + (lane & 7);
            int bcol = kk + ((lane >> 3) & 1) * 8;
            unsigned sb = (unsigned)__cvta_generic_to_shared(Wh + brow * ASTR + bcol);
            asm volatile("ldmatrix.sync.aligned.m8n8.x2.shared.b16 {%0,%1}, [%2];"
                         : "=r"(b0), "=r"(b1) : "r"(sb));
            asm volatile("mma.sync.aligned.m16n8k16.row.col.f32.f16.f16.f32 "
                         "{%0,%1,%2,%3}, {%4,%5,%6,%7}, {%8,%9}, {%0,%1,%2,%3};"
                         : "+f"(acc[nt][0]), "+f"(acc[nt][1]), "+f"(acc[nt][2]), "+f"(acc[nt][3])
                         : "r"(a0), "r"(a1), "r"(a2), "r"(a3), "r"(b0), "r"(b1));
        }
    }

    // accumulator fragment: {c0,c1} node row = lane/4,   cols (lane%4)*2, +1
    //                       {c2,c3} node row = lane/4+8, same cols
    const int r = lane >> 2;
    const int cq = (lane & 3) * 2;
    const int gA = base + m0 + r;
    const int gB = gA + 8;

    if (EPI == 0) {
        float nmA = (gA < N) ? g_norm[gA] : 0.f;
        float nmB = (gB < N) ? g_norm[gB] : 0.f;
#pragma unroll
        for (int nt = 0; nt < 8; nt++) {
            int c = nt * 8 + cq;
            float bx = Bsm[c], by = Bsm[c + 1];
            if (gA < N) {
                __half2 h = __floats2half2_rn(fmaxf(acc[nt][0] + bx, 0.f) * nmA,
                                              fmaxf(acc[nt][1] + by, 0.f) * nmA);
                *(__half2*)(g_t + (long long)gA * 64 + c) = h;
            }
            if (gB < N) {
                __half2 h = __floats2half2_rn(fmaxf(acc[nt][2] + bx, 0.f) * nmB,
                                              fmaxf(acc[nt][3] + by, 0.f) * nmB);
                *(__half2*)(g_t + (long long)gB * 64 + c) = h;
            }
        }
    } else if (EPI == 2) {
#pragma unroll
        for (int nt = 0; nt < 8; nt++) {
            int c = nt * 8 + cq;
            float bx = Bsm[c], by = Bsm[c + 1];
            if (gA < N) {
                float2 v = make_float2(1.f / (1.f + expf(-(acc[nt][0] + bx))),
                                       1.f / (1.f + expf(-(acc[nt][1] + by))));
                *(float2*)(o0 + (long long)gA * 64 + c) = v;
            }
            if (gB < N) {
                float2 v = make_float2(1.f / (1.f + expf(-(acc[nt][2] + bx))),
                                       1.f / (1.f + expf(-(acc[nt][3] + by))));
                *(float2*)(o0 + (long long)gB * 64 + c) = v;
            }
        }
    } else {
        // EPI 1: mu = nt 0..3 (cols 0..31), lv = nt 4..7 (cols 32..63)
        float nmA = (gA < N) ? g_norm[gA] : 0.f;
        float nmB = (gB < N) ? g_norm[gB] : 0.f;
#pragma unroll
        for (int nt = 0; nt < 4; nt++) {
            int c = nt * 8 + cq;
            float bm0 = Bsm[c], bm1 = Bsm[c + 1];
            float bl0 = Bsm[32 + c], bl1 = Bsm[32 + c + 1];
            if (gA < N) {
                long long idx = (long long)gA * 32 + c;
                float mu0 = acc[nt][0] + bm0, mu1 = acc[nt][1] + bm1;
                float lv0 = acc[nt + 4][0] + bl0, lv1 = acc[nt + 4][1] + bl1;
                if (have) {
                    *(float2*)(o0 + idx) = make_float2(mu0, mu1);
                    *(float2*)(o1 + idx) = make_float2(lv0, lv1);
                }
                float2 ep = *(const float2*)(eps + idx);
                float z0 = ep.x * expf(0.5f * lv0) + mu0;
                float z1 = ep.y * expf(0.5f * lv1) + mu1;
                *(__half2*)(g_t + idx) = __floats2half2_rn(z0 * nmA, z1 * nmA);
            }
            if (gB < N) {
                long long idx = (long long)gB * 32 + c;
                float mu0 = acc[nt][2] + bm0, mu1 = acc[nt][3] + bm1;
                float lv0 = acc[nt + 4][2] + bl0, lv1 = acc[nt + 4][3] + bl1;
                if (have) {
                    *(float2*)(o0 + idx) = make_float2(mu0, mu1);
                    *(float2*)(o1 + idx) = make_float2(lv0, lv1);
                }
                float2 ep = *(const float2*)(eps + idx);
                float z0 = ep.x * expf(0.5f * lv0) + mu0;
                float z1 = ep.y * expf(0.5f * lv1) + mu1;
                *(__half2*)(g_t + idx) = __floats2half2_rn(z0 * nmB, z1 * nmB);
            }
        }
    }
}

// ---------------- launch --------------------------------------------------------
extern "C" void kernel_launch(void* const* d_in, const int* in_sizes, int n_in,
                              void* d_out, int out_size) {
    const int T = 256;
    auto G = [&](long long c) { return (int)((c + T - 1) / T); };
    float* outp = (float*)d_out;

    int N = in_sizes[0] / 64;
    int E = in_sizes[1];
    if (N > MAXN) N = MAXN;
    if (E > MAXE) E = MAXE;
    bool full_out = (out_size >= N * 128);
    (void)n_in;

    const float* x   = (const float*)d_in[0];
    const int* esrc  = (const int*)d_in[1];
    const int* edst  = (const int*)d_in[2];
    const float* eps = (const float*)d_in[3];
    const float* W1  = (const float*)d_in[4];  const float* b1  = (const float*)d_in[5];
    const float* W2  = (const float*)d_in[6];  const float* b2  = (const float*)d_in[7];
    const float* W31 = (const float*)d_in[8];  const float* b31 = (const float*)d_in[9];
    const float* W32 = (const float*)d_in[10]; const float* b32 = (const float*)d_in[11];
    const float* W4  = (const float*)d_in[12]; const float* b4  = (const float*)d_in[13];
    const float* W5  = (const float*)d_in[14]; const float* b5  = (const float*)d_in[15];
    const float* W6  = (const float*)d_in[16]; const float* b6  = (const float*)d_in[17];

    float* recon = outp;                          // N x 64
    float* d_mu  = outp + (long long)N * 64;      // N x 32
    float* d_lv  = d_mu + (long long)N * 32;      // N x 32

    // smem: (128 + 64) * (K+8) halves + 64 floats
    const int SM64 = (192 * 72) * 2 + 256;   // 27904 B
    const int SM32 = (192 * 40) * 2 + 256;   // 15616 B

    if (out_size != N * 128)
        kfill_out<<<G(out_size), T>>>(outp, out_size);

    kz_deg<<<G(N), T>>>(N);
    kdeg<<<G(E), T>>>(edst, E);

    int nb = (N + 1023) / 1024;
    kscan1<<<nb, 1024>>>(N);
    kscan2<<<1, 1024>>>(nb, N);
    kscan3<<<nb, 1024>>>(N);      // also computes g_norm

    kcsr<<<G(E), T>>>(esrc, edst, E);

    kt0<<<G((long long)N * 64), T>>>(x, N * 64);

    const int AB = (N + 7) / 8;
    const int GB = (N + 127) / 128;
    int hv = full_out ? 1 : 0;

    kagg64<<<AB, 256>>>(N);
    kgemm<64, 0><<<GB, 256, SM64>>>(W1, nullptr, b1, nullptr, nullptr, nullptr, nullptr, N, 0);
    kagg64<<<AB, 256>>>(N);
    kgemm<64, 0><<<GB, 256, SM64>>>(W2, nullptr, b2, nullptr, nullptr, nullptr, nullptr, N, 0);
    kagg64<<<AB, 256>>>(N);
    kgemm<64, 1><<<GB, 256, SM64>>>(W31, W32, b31, b32, d_mu, d_lv, eps, N, hv);
    kagg32<<<AB, 256>>>(N);
    kgemm<32, 0><<<GB, 256, SM32>>>(W4, nullptr, b4, nullptr, nullptr, nullptr, nullptr, N, 0);
    kagg64<<<AB, 256>>>(N);
    kgemm<64, 0><<<GB, 256, SM64>>>(W5, nullptr, b5, nullptr, nullptr, nullptr, nullptr, N, 0);
    kagg64<<<AB, 256>>>(N);
    kgemm<64, 2><<<GB, 256, SM64>>>(W6, nullptr, b6, nullptr, recon, nullptr, nullptr, N, 0);
}

// round 17
// speedup vs baseline: 1.1276x; 1.1276x over previous
#include <cuda_runtime.h>
#include <cuda_fp16.h>
#include <math.h>

#define MAXN 100000
#define MAXE 1600000

// ---------------- static device scratch (device-code use ONLY) -----------------
__device__ int    g_deg[MAXN];
__device__ int    g_off[MAXN + 1];
__device__ int    g_cur[MAXN];
__device__ int    g_part[1024];
__device__ int    g_srcA[MAXE];       // CSR: incoming-edge sources per dst node
__device__ float  g_norm[MAXN];
__device__ __half g_t[MAXN * 64];     // messages: h * norm (fp16)
__device__ __half g_agg[MAXN * 64];   // aggregation * norm (fp16 rn — bit-identical to GEMM staging)

// ---------------- graph preprocessing ------------------------------------------
__global__ void kz_deg(int n) {
    int i = blockIdx.x * blockDim.x + threadIdx.x;
    if (i < n) g_deg[i] = 0;
}
__global__ void kfill_out(float* __restrict__ p, int c) {
    int i = blockIdx.x * blockDim.x + threadIdx.x;
    if (i < c) p[i] = 0.0f;
}
__global__ void kdeg(const int* __restrict__ dst, int E) {
    int e = blockIdx.x * blockDim.x + threadIdx.x;
    if (e < E) atomicAdd(&g_deg[dst[e]], 1);
}

// ---- 3-pass exclusive scan of g_deg[0..N) -> g_off, g_cur (+norm in pass 3) ----
__global__ void kscan1(int N) {
    __shared__ int sh[1024];
    int tid = threadIdx.x;
    int i = blockIdx.x * 1024 + tid;
    int v = (i < N) ? g_deg[i] : 0;
    sh[tid] = v;
    __syncthreads();
    for (int off = 1; off < 1024; off <<= 1) {
        int t = (tid >= off) ? sh[tid - off] : 0;
        __syncthreads();
        sh[tid] += t;
        __syncthreads();
    }
    if (i < N) g_off[i] = sh[tid] - v;
    if (tid == 1023) g_part[blockIdx.x] = sh[1023];
}
__global__ void kscan2(int nb, int N) {
    __shared__ int sh[1024];
    int tid = threadIdx.x;
    int v = (tid < nb) ? g_part[tid] : 0;
    sh[tid] = v;
    __syncthreads();
    for (int off = 1; off < 1024; off <<= 1) {
        int t = (tid >= off) ? sh[tid - off] : 0;
        __syncthreads();
        sh[tid] += t;
        __syncthreads();
    }
    if (tid < nb) g_part[tid] = sh[tid] - v;
    if (tid == 1023) g_off[N] = sh[1023];
}
__global__ void kscan3(int N) {
    int i = blockIdx.x * 1024 + threadIdx.x;
    if (i < N) {
        int o = g_off[i] + g_part[blockIdx.x];
        g_off[i] = o;
        g_cur[i] = o;
        g_norm[i] = rsqrtf(fmaxf((float)g_deg[i], 1.0f));
    }
}

__global__ void kcsr(const int* __restrict__ src, const int* __restrict__ dst, int E) {
    int e = blockIdx.x * blockDim.x + threadIdx.x;
    if (e < E) {
        int p = atomicAdd(&g_cur[dst[e]], 1);
        g_srcA[p] = src[e];
    }
}

__global__ void kt0(const float* __restrict__ x, int c) {
    int i = blockIdx.x * blockDim.x + threadIdx.x;
    if (i < c) g_t[i] = __float2half_rn(x[i] * g_norm[i >> 6]);
}

// ---------------- aggregation (pull over CSR, fp16 msgs, fp32 accum) ------------
// one warp per dst node, TWO edges per warp-iteration:
//   lanes 0-15 process even edges, lanes 16-31 odd edges; lane owns 4 feats (uint2).
// Final shfl_xor(16) combines even/odd partial sums; lanes 0-15 store.
__global__ __launch_bounds__(256) void kagg64(int N) {
    int n = blockIdx.x * 8 + (threadIdx.x >> 5);
    if (n >= N) return;
    int lane = threadIdx.x & 31;
    int hf = lane >> 4;            // 0: even edges, 1: odd edges
    int l16 = lane & 15;           // feature group (4 feats = 1 uint2)
    int b = g_off[n], e = g_off[n + 1];
    const uint2* tp = (const uint2*)g_t;   // row = 16 uint2 (64 halves)

    float a0 = 0.f, a1 = 0.f, a2 = 0.f, a3 = 0.f;
    int i = b + hf;
    for (; i + 6 < e; i += 8) {            // 8 edges per pass (4 per half)
        int s0 = g_srcA[i],     s1 = g_srcA[i + 2];
        int s2 = g_srcA[i + 4], s3 = g_srcA[i + 6];
        uint2 v0 = tp[s0 * 16 + l16];
        uint2 v1 = tp[s1 * 16 + l16];
        uint2 v2 = tp[s2 * 16 + l16];
        uint2 v3 = tp[s3 * 16 + l16];
        float2 f;
        f = __half22float2(*(__half2*)&v0.x); a0 += f.x; a1 += f.y;
        f = __half22float2(*(__half2*)&v0.y); a2 += f.x; a3 += f.y;
        f = __half22float2(*(__half2*)&v1.x); a0 += f.x; a1 += f.y;
        f = __half22float2(*(__half2*)&v1.y); a2 += f.x; a3 += f.y;
        f = __half22float2(*(__half2*)&v2.x); a0 += f.x; a1 += f.y;
        f = __half22float2(*(__half2*)&v2.y); a2 += f.x; a3 += f.y;
        f = __half22float2(*(__half2*)&v3.x); a0 += f.x; a1 += f.y;
        f = __half22float2(*(__half2*)&v3.y); a2 += f.x; a3 += f.y;
    }
    for (; i < e; i += 2) {
        int s = g_srcA[i];
        uint2 v = tp[s * 16 + l16];
        float2 f;
        f = __half22float2(*(__half2*)&v.x); a0 += f.x; a1 += f.y;
        f = __half22float2(*(__half2*)&v.y); a2 += f.x; a3 += f.y;
    }
    a0 += __shfl_xor_sync(0xffffffffu, a0, 16);
    a1 += __shfl_xor_sync(0xffffffffu, a1, 16);
    a2 += __shfl_xor_sync(0xffffffffu, a2, 16);
    a3 += __shfl_xor_sync(0xffffffffu, a3, 16);
    if (hf == 0) {
        float nm = g_norm[n];
        __half2 h0 = __floats2half2_rn(a0 * nm, a1 * nm);
        __half2 h1 = __floats2half2_rn(a2 * nm, a3 * nm);
        uint2 out;
        out.x = *(unsigned*)&h0;
        out.y = *(unsigned*)&h1;
        ((uint2*)g_agg)[n * 16 + l16] = out;
    }
}

// 32 feats: lane owns 1 half2 (2 feats); same even/odd edge split.
__global__ __launch_bounds__(256) void kagg32(int N) {
    int n = blockIdx.x * 8 + (threadIdx.x >> 5);
    if (n >= N) return;
    int lane = threadIdx.x & 31;
    int hf = lane >> 4;
    int l16 = lane & 15;
    int b = g_off[n], e = g_off[n + 1];
    const __half2* tp = (const __half2*)g_t;  // row = 16 half2 (32 halves)

    float ax = 0.f, ay = 0.f;
    int i = b + hf;
    for (; i + 6 < e; i += 8) {
        int s0 = g_srcA[i],     s1 = g_srcA[i + 2];
        int s2 = g_srcA[i + 4], s3 = g_srcA[i + 6];
        float2 f0 = __half22float2(tp[s0 * 16 + l16]);
        float2 f1 = __half22float2(tp[s1 * 16 + l16]);
        float2 f2 = __half22float2(tp[s2 * 16 + l16]);
        float2 f3 = __half22float2(tp[s3 * 16 + l16]);
        ax += (f0.x + f1.x) + (f2.x + f3.x);
        ay += (f0.y + f1.y) + (f2.y + f3.y);
    }
    for (; i < e; i += 2) {
        float2 f = __half22float2(tp[g_srcA[i] * 16 + l16]);
        ax += f.x; ay += f.y;
    }
    ax += __shfl_xor_sync(0xffffffffu, ax, 16);
    ay += __shfl_xor_sync(0xffffffffu, ay, 16);
    if (hf == 0) {
        float nm = g_norm[n];
        ((__half2*)g_agg)[n * 16 + l16] = __floats2half2_rn(ax * nm, ay * nm);
    }
}

// ---------------- tensor-core GEMM (HMMA fp16 x fp16 -> fp32) -------------------
// 256 threads = 8 warps; tile 128 nodes x 64 outs; warp w owns nodes [w*16, w*16+16).
template <int K, int EPI>
__global__ __launch_bounds__(256) void kgemm(
    const float* __restrict__ Wa, const float* __restrict__ Wb,
    const float* __restrict__ bias0, const float* __restrict__ bias1,
    float* __restrict__ o0, float* __restrict__ o1, const float* __restrict__ eps,
    int N, int have)
{
    constexpr int ASTR = K + 8;                 // halves, keeps rows 16B aligned
    extern __shared__ __half smh[];
    __half* Ah = smh;                           // 128 * ASTR
    __half* Wh = smh + 128 * ASTR;              // 64 * ASTR
    float* Bsm = (float*)(Wh + 64 * ASTR);      // 64
    const int tid = threadIdx.x;
    const int base = blockIdx.x * 128;

    // stage A tile: straight 16B copies from fp16 g_agg
    for (int q = tid; q < 128 * (K / 8); q += 256) {
        int node = q / (K / 8), seg = q % (K / 8);
        int gn = base + node;
        uint4 v = make_uint4(0u, 0u, 0u, 0u);
        if (gn < N) v = *(const uint4*)(g_agg + (long long)gn * K + seg * 8);
        *(uint4*)(Ah + node * ASTR + seg * 8) = v;
    }
    // stage W (fp32 -> fp16)
    for (int q = tid; q < 64 * (K / 8); q += 256) {
        int o = q / (K / 8), seg = q % (K / 8);
        const float* Wrow;
        if (EPI == 1) Wrow = (o < 32) ? (Wa + o * 64) : (Wb + (o - 32) * 64);
        else          Wrow = Wa + o * K;
        float4 v0 = *(const float4*)(Wrow + seg * 8);
        float4 v1 = *(const float4*)(Wrow + seg * 8 + 4);
        __half2 h[4];
        h[0] = __floats2half2_rn(v0.x, v0.y);
        h[1] = __floats2half2_rn(v0.z, v0.w);
        h[2] = __floats2half2_rn(v1.x, v1.y);
        h[3] = __floats2half2_rn(v1.z, v1.w);
        *(uint4*)(Wh + o * ASTR + seg * 8) = *(uint4*)h;
    }
    if (tid < 64) {
        if (EPI == 1) Bsm[tid] = (tid < 32) ? bias0[tid] : bias1[tid - 32];
        else          Bsm[tid] = bias0[tid];
    }
    __syncthreads();

    const int w = tid >> 5, lane = tid & 31;
    const int m0 = w * 16;

    float acc[8][4];
#pragma unroll
    for (int nt = 0; nt < 8; nt++)
#pragma unroll
        for (int j = 0; j < 4; j++) acc[nt][j] = 0.f;

#pragma unroll
    for (int kk = 0; kk < K; kk += 16) {
        unsigned a0, a1, a2, a3;
        {
            int row = m0 + (lane & 15);
            int col = kk + ((lane >> 4) << 3);
            unsigned sa = (unsigned)__cvta_generic_to_shared(Ah + row * ASTR + col);
            asm volatile("ldmatrix.sync.aligned.m8n8.x4.shared.b16 {%0,%1,%2,%3}, [%4];"
                         : "=r"(a0), "=r"(a1), "=r"(a2), "=r"(a3) : "r"(sa));
        }
#pragma unroll
        for (int nt = 0; nt < 8; nt++) {
            unsigned b0, b1;
            int brow = nt * 8 + (lane & 7);
            int bcol = kk + ((lane >> 3) & 1) * 8;
            unsigned sb = (unsigned)__cvta_generic_to_shared(Wh + brow * ASTR + bcol);
            asm volatile("ldmatrix.sync.aligned.m8n8.x2.shared.b16 {%0,%1}, [%2];"
                         : "=r"(b0), "=r"(b1) : "r"(sb));
            asm volatile("mma.sync.aligned.m16n8k16.row.col.f32.f16.f16.f32 "
                         "{%0,%1,%2,%3}, {%4,%5,%6,%7}, {%8,%9}, {%0,%1,%2,%3};"
                         : "+f"(acc[nt][0]), "+f"(acc[nt][1]), "+f"(acc[nt][2]), "+f"(acc[nt][3])
                         : "r"(a0), "r"(a1), "r"(a2), "r"(a3), "r"(b0), "r"(b1));
        }
    }

    // accumulator fragment: {c0,c1} node row = lane/4,   cols (lane%4)*2, +1
    //                       {c2,c3} node row = lane/4+8, same cols
    const int r = lane >> 2;
    const int cq = (lane & 3) * 2;
    const int gA = base + m0 + r;
    const int gB = gA + 8;

    if (EPI == 0) {
        float nmA = (gA < N) ? g_norm[gA] : 0.f;
        float nmB = (gB < N) ? g_norm[gB] : 0.f;
#pragma unroll
        for (int nt = 0; nt < 8; nt++) {
            int c = nt * 8 + cq;
            float bx = Bsm[c], by = Bsm[c + 1];
            if (gA < N) {
                __half2 h = __floats2half2_rn(fmaxf(acc[nt][0] + bx, 0.f) * nmA,
                                              fmaxf(acc[nt][1] + by, 0.f) * nmA);
                *(__half2*)(g_t + (long long)gA * 64 + c) = h;
            }
            if (gB < N) {
                __half2 h = __floats2half2_rn(fmaxf(acc[nt][2] + bx, 0.f) * nmB,
                                              fmaxf(acc[nt][3] + by, 0.f) * nmB);
                *(__half2*)(g_t + (long long)gB * 64 + c) = h;
            }
        }
    } else if (EPI == 2) {
#pragma unroll
        for (int nt = 0; nt < 8; nt++) {
            int c = nt * 8 + cq;
            float bx = Bsm[c], by = Bsm[c + 1];
            if (gA < N) {
                float2 v = make_float2(1.f / (1.f + expf(-(acc[nt][0] + bx))),
                                       1.f / (1.f + expf(-(acc[nt][1] + by))));
                *(float2*)(o0 + (long long)gA * 64 + c) = v;
            }
            if (gB < N) {
                float2 v = make_float2(1.f / (1.f + expf(-(acc[nt][2] + bx))),
                                       1.f / (1.f + expf(-(acc[nt][3] + by))));
                *(float2*)(o0 + (long long)gB * 64 + c) = v;
            }
        }
    } else {
        // EPI 1: mu = nt 0..3 (cols 0..31), lv = nt 4..7 (cols 32..63)
        float nmA = (gA < N) ? g_norm[gA] : 0.f;
        float nmB = (gB < N) ? g_norm[gB] : 0.f;
#pragma unroll
        for (int nt = 0; nt < 4; nt++) {
            int c = nt * 8 + cq;
            float bm0 = Bsm[c], bm1 = Bsm[c + 1];
            float bl0 = Bsm[32 + c], bl1 = Bsm[32 + c + 1];
            if (gA < N) {
                long long idx = (long long)gA * 32 + c;
                float mu0 = acc[nt][0] + bm0, mu1 = acc[nt][1] + bm1;
                float lv0 = acc[nt + 4][0] + bl0, lv1 = acc[nt + 4][1] + bl1;
                if (have) {
                    *(float2*)(o0 + idx) = make_float2(mu0, mu1);
                    *(float2*)(o1 + idx) = make_float2(lv0, lv1);
                }
                float2 ep = *(const float2*)(eps + idx);
                float z0 = ep.x * expf(0.5f * lv0) + mu0;
                float z1 = ep.y * expf(0.5f * lv1) + mu1;
                *(__half2*)(g_t + idx) = __floats2half2_rn(z0 * nmA, z1 * nmA);
            }
            if (gB < N) {
                long long idx = (long long)gB * 32 + c;
                float mu0 = acc[nt][2] + bm0, mu1 = acc[nt][3] + bm1;
                float lv0 = acc[nt + 4][2] + bl0, lv1 = acc[nt + 4][3] + bl1;
                if (have) {
                    *(float2*)(o0 + idx) = make_float2(mu0, mu1);
                    *(float2*)(o1 + idx) = make_float2(lv0, lv1);
                }
                float2 ep = *(const float2*)(eps + idx);
                float z0 = ep.x * expf(0.5f * lv0) + mu0;
                float z1 = ep.y * expf(0.5f * lv1) + mu1;
                *(__half2*)(g_t + idx) = __floats2half2_rn(z0 * nmB, z1 * nmB);
            }
        }
    }
}

// ---------------- launch --------------------------------------------------------
extern "C" void kernel_launch(void* const* d_in, const int* in_sizes, int n_in,
                              void* d_out, int out_size) {
    const int T = 256;
    auto G = [&](long long c) { return (int)((c + T - 1) / T); };
    float* outp = (float*)d_out;

    int N = in_sizes[0] / 64;
    int E = in_sizes[1];
    if (N > MAXN) N = MAXN;
    if (E > MAXE) E = MAXE;
    bool full_out = (out_size >= N * 128);
    (void)n_in;

    const float* x   = (const float*)d_in[0];
    const int* esrc  = (const int*)d_in[1];
    const int* edst  = (const int*)d_in[2];
    const float* eps = (const float*)d_in[3];
    const float* W1  = (const float*)d_in[4];  const float* b1  = (const float*)d_in[5];
    const float* W2  = (const float*)d_in[6];  const float* b2  = (const float*)d_in[7];
    const float* W31 = (const float*)d_in[8];  const float* b31 = (const float*)d_in[9];
    const float* W32 = (const float*)d_in[10]; const float* b32 = (const float*)d_in[11];
    const float* W4  = (const float*)d_in[12]; const float* b4  = (const float*)d_in[13];
    const float* W5  = (const float*)d_in[14]; const float* b5  = (const float*)d_in[15];
    const float* W6  = (const float*)d_in[16]; const float* b6  = (const float*)d_in[17];

    float* recon = outp;                          // N x 64
    float* d_mu  = outp + (long long)N * 64;      // N x 32
    float* d_lv  = d_mu + (long long)N * 32;      // N x 32

    // smem: (128 + 64) * (K+8) halves + 64 floats
    const int SM64 = (192 * 72) * 2 + 256;   // 27904 B
    const int SM32 = (192 * 40) * 2 + 256;   // 15616 B

    if (out_size != N * 128)
        kfill_out<<<G(out_size), T>>>(outp, out_size);

    kz_deg<<<G(N), T>>>(N);
    kdeg<<<G(E), T>>>(edst, E);

    int nb = (N + 1023) / 1024;
    kscan1<<<nb, 1024>>>(N);
    kscan2<<<1, 1024>>>(nb, N);
    kscan3<<<nb, 1024>>>(N);      // also computes g_norm

    kcsr<<<G(E), T>>>(esrc, edst, E);

    kt0<<<G((long long)N * 64), T>>>(x, N * 64);

    const int AB = (N + 7) / 8;
    const int GB = (N + 127) / 128;
    int hv = full_out ? 1 : 0;

    kagg64<<<AB, 256>>>(N);
    kgemm<64, 0><<<GB, 256, SM64>>>(W1, nullptr, b1, nullptr, nullptr, nullptr, nullptr, N, 0);
    kagg64<<<AB, 256>>>(N);
    kgemm<64, 0><<<GB, 256, SM64>>>(W2, nullptr, b2, nullptr, nullptr, nullptr, nullptr, N, 0);
    kagg64<<<AB, 256>>>(N);
    kgemm<64, 1><<<GB, 256, SM64>>>(W31, W32, b31, b32, d_mu, d_lv, eps, N, hv);
    kagg32<<<AB, 256>>>(N);
    kgemm<32, 0><<<GB, 256, SM32>>>(W4, nullptr, b4, nullptr, nullptr, nullptr, nullptr, N, 0);
    kagg64<<<AB, 256>>>(N);
    kgemm<64, 0><<<GB, 256, SM64>>>(W5, nullptr, b5, nullptr, nullptr, nullptr, nullptr, N, 0);
    kagg64<<<AB, 256>>>(N);
    kgemm<64, 2><<<GB, 256, SM64>>>(W6, nullptr, b6, nullptr, recon, nullptr, nullptr, N, 0);
}